// round 5
// baseline (speedup 1.0000x reference)
#include <cuda_runtime.h>

// Problem constants
constexpr int Bn   = 128;
constexpr int Ln   = 336;
constexpr int Nn   = 321;
constexpr int En   = 128;
constexpr int LATn = 64;

constexpr int HN    = Bn * Nn * En;    // 5,259,264
constexpr int LATSZ = Bn * Nn * LATn;  // 2,629,632

// Scratch: x transposed to [B, N, L] (55 MB, static device global — allowed)
__device__ static float g_xp[(size_t)Bn * Nn * Ln];

// ---------------------------------------------------------------------------
// f32x2 packed-math helpers
// ---------------------------------------------------------------------------
typedef unsigned long long u64t;

__device__ __forceinline__ u64t ffma2(u64t a, u64t b, u64t c) {
    u64t d;
    asm("fma.rn.f32x2 %0, %1, %2, %3;" : "=l"(d) : "l"(a), "l"(b), "l"(c));
    return d;
}
__device__ __forceinline__ u64t dup2(float w) {
    u64t d;
    asm("mov.b64 %0, {%1, %1};" : "=l"(d) : "f"(w));
    return d;
}
__device__ __forceinline__ float2 unpk(u64t v) {
    float2 r;
    asm("mov.b64 {%0, %1}, %2;" : "=f"(r.x), "=f"(r.y) : "l"(v));
    return r;
}

// ---------------------------------------------------------------------------
// Kernel 1: transpose x [B, L, N] -> g_xp [B, N, L]   (unchanged, ~22us)
// ---------------------------------------------------------------------------
__global__ void transpose_kernel(const float* __restrict__ x) {
    __shared__ float tile[32][33];
    const int b  = blockIdx.z;
    const int n0 = blockIdx.x * 32;
    const int l0 = blockIdx.y * 32;

#pragma unroll
    for (int i = 0; i < 4; i++) {
        int l  = l0 + threadIdx.y + i * 8;
        int nn = n0 + threadIdx.x;
        if (l < Ln && nn < Nn)
            tile[threadIdx.y + i * 8][threadIdx.x] = x[((size_t)b * Ln + l) * Nn + nn];
    }
    __syncthreads();
#pragma unroll
    for (int i = 0; i < 4; i++) {
        int nn = n0 + threadIdx.y + i * 8;
        int l  = l0 + threadIdx.x;
        if (nn < Nn && l < Ln)
            g_xp[((size_t)b * Nn + nn) * Ln + l] = tile[threadIdx.x][threadIdx.y + i * 8];
    }
}

// ---------------------------------------------------------------------------
// Kernel 2: per-channel GEMM, one CTA per n.
//   h[b,e] = sum_l xp[b,n,l] * W_embed[n,l,e] + b_embed[n,e]
//   h_hat  = sigmoid(time_x) * h
// M=128(b) x N=128(e), K=336 in 21 tiles of 16.
// A is staged in smem PRE-DUPLICATED as f32x2 pairs -> zero MOVs in mainloop.
// ---------------------------------------------------------------------------
constexpr int KT = 16;

__global__ void __launch_bounds__(256, 2) embed_kernel(
    const float* __restrict__ W_embed, const float* __restrict__ b_embed,
    const float* __restrict__ time_x,
    float* __restrict__ h_out, float* __restrict__ hhat_out)
{
    __shared__ u64t  xs2[KT][128];   // 16 KB : (x,x) duplicated pairs, [k][m]
    __shared__ float ws [KT][128];   // 8 KB  : [k][e]

    const int n = blockIdx.x;
    const int t = threadIdx.x;
    // compute mapping: 16 m-tiles x 16 e-tiles of 8x8
    const int te = t & 15, tm = t >> 4;
    const int m_base = tm * 8, e_base = te * 8;
    // A-fill mapping: thread -> (row mf, k-half khf)
    const int mf  = t >> 1;
    const int khf = (t & 1) * 8;
    // W-fill mapping: thread -> (k row kwf, e-oct ewf)
    const int kwf = t >> 4;
    const int ewf = (t & 15) * 8;

    const float* xrow  = g_xp + ((size_t)mf * Nn + n) * Ln;
    const float* wbase = W_embed + (size_t)n * Ln * En;

    u64t acc[8][4];
#pragma unroll
    for (int i = 0; i < 8; i++)
#pragma unroll
        for (int j = 0; j < 4; j++) acc[i][j] = 0ULL;

    // prologue: load tile 0 into registers
    float4 xa = *(const float4*)(xrow + khf);
    float4 xb = *(const float4*)(xrow + khf + 4);
    float4 wa = *(const float4*)(wbase + (size_t)kwf * En + ewf);
    float4 wb = *(const float4*)(wbase + (size_t)kwf * En + ewf + 4);

    for (int kt = 0; kt < Ln; kt += KT) {
        // store staged tile (A duplicated)
        xs2[khf + 0][mf] = dup2(xa.x);
        xs2[khf + 1][mf] = dup2(xa.y);
        xs2[khf + 2][mf] = dup2(xa.z);
        xs2[khf + 3][mf] = dup2(xa.w);
        xs2[khf + 4][mf] = dup2(xb.x);
        xs2[khf + 5][mf] = dup2(xb.y);
        xs2[khf + 6][mf] = dup2(xb.z);
        xs2[khf + 7][mf] = dup2(xb.w);
        *(float4*)&ws[kwf][ewf]     = wa;
        *(float4*)&ws[kwf][ewf + 4] = wb;
        __syncthreads();

        // prefetch next tile into registers (overlaps compute below)
        if (kt + KT < Ln) {
            xa = *(const float4*)(xrow + kt + KT + khf);
            xb = *(const float4*)(xrow + kt + KT + khf + 4);
            wa = *(const float4*)(wbase + (size_t)(kt + KT + kwf) * En + ewf);
            wb = *(const float4*)(wbase + (size_t)(kt + KT + kwf) * En + ewf + 4);
        }

#pragma unroll
        for (int kk = 0; kk < KT; kk++) {
            const ulonglong2* xp = (const ulonglong2*)&xs2[kk][m_base];
            ulonglong2 x01 = xp[0], x23 = xp[1], x45 = xp[2], x67 = xp[3];
            const ulonglong2* wp = (const ulonglong2*)&ws[kk][e_base];
            ulonglong2 w03 = wp[0], w47 = wp[1];
            u64t xd[8] = {x01.x, x01.y, x23.x, x23.y, x45.x, x45.y, x67.x, x67.y};
            u64t wpr[4] = {w03.x, w03.y, w47.x, w47.y};
#pragma unroll
            for (int i = 0; i < 8; i++)
#pragma unroll
                for (int j = 0; j < 4; j++)
                    acc[i][j] = ffma2(wpr[j], xd[i], acc[i][j]);
        }
        __syncthreads();
    }

    // epilogue: bias + h, sigmoid(time_x)*h
    float4 ba = *(const float4*)(b_embed + n * En + e_base);
    float4 bb = *(const float4*)(b_embed + n * En + e_base + 4);
#pragma unroll
    for (int i = 0; i < 8; i++) {
        const size_t idx = ((size_t)(m_base + i) * Nn + n) * En + e_base;
        float2 p0 = unpk(acc[i][0]), p1 = unpk(acc[i][1]);
        float2 p2 = unpk(acc[i][2]), p3 = unpk(acc[i][3]);
        float4 h0 = {p0.x + ba.x, p0.y + ba.y, p1.x + ba.z, p1.y + ba.w};
        float4 h1 = {p2.x + bb.x, p2.y + bb.y, p3.x + bb.z, p3.y + bb.w};
        *(float4*)(h_out + idx)     = h0;
        *(float4*)(h_out + idx + 4) = h1;
        float4 t0 = *(const float4*)(time_x + idx);
        float4 t1 = *(const float4*)(time_x + idx + 4);
        float4 g0 = {h0.x / (1.0f + __expf(-t0.x)), h0.y / (1.0f + __expf(-t0.y)),
                     h0.z / (1.0f + __expf(-t0.z)), h0.w / (1.0f + __expf(-t0.w))};
        float4 g1 = {h1.x / (1.0f + __expf(-t1.x)), h1.y / (1.0f + __expf(-t1.y)),
                     h1.z / (1.0f + __expf(-t1.z)), h1.w / (1.0f + __expf(-t1.w))};
        *(float4*)(hhat_out + idx)     = g0;
        *(float4*)(hhat_out + idx + 4) = g1;
    }
}

// ---------------------------------------------------------------------------
// Kernel 3: heads, one CTA per n. M=128(b) x N=128(mu64|var64), K=128(e).
// Same duplicated-A f32x2 mainloop.
// ---------------------------------------------------------------------------
__global__ void __launch_bounds__(256, 2) heads_kernel(
    const float* __restrict__ W_mu, const float* __restrict__ b_mu,
    const float* __restrict__ W_var, const float* __restrict__ b_var,
    const float* __restrict__ hhat,
    float* __restrict__ mu_out, float* __restrict__ var_out)
{
    __shared__ u64t  xs2[KT][128];
    __shared__ float ws [KT][128];   // [k][ mu cols 0..63 | var cols 64..127 ]

    const int n = blockIdx.x;
    const int t = threadIdx.x;
    const int te = t & 15, tm = t >> 4;
    const int m_base = tm * 8, e_base = te * 8;
    const int mf  = t >> 1;
    const int khf = (t & 1) * 8;
    const int kwf = t >> 4;
    const int cwf = (t & 15) * 8;

    const float* arow = hhat + ((size_t)mf * Nn + n) * En;
    const float* wsrc = (cwf < 64)
        ? (W_mu  + ((size_t)n * En) * LATn + cwf)
        : (W_var + ((size_t)n * En) * LATn + (cwf - 64));

    u64t acc[8][4];
#pragma unroll
    for (int i = 0; i < 8; i++)
#pragma unroll
        for (int j = 0; j < 4; j++) acc[i][j] = 0ULL;

    float4 xa = *(const float4*)(arow + khf);
    float4 xb = *(const float4*)(arow + khf + 4);
    float4 wa = *(const float4*)(wsrc + (size_t)kwf * LATn);
    float4 wb = *(const float4*)(wsrc + (size_t)kwf * LATn + 4);

    for (int kt = 0; kt < En; kt += KT) {
        xs2[khf + 0][mf] = dup2(xa.x);
        xs2[khf + 1][mf] = dup2(xa.y);
        xs2[khf + 2][mf] = dup2(xa.z);
        xs2[khf + 3][mf] = dup2(xa.w);
        xs2[khf + 4][mf] = dup2(xb.x);
        xs2[khf + 5][mf] = dup2(xb.y);
        xs2[khf + 6][mf] = dup2(xb.z);
        xs2[khf + 7][mf] = dup2(xb.w);
        *(float4*)&ws[kwf][cwf]     = wa;
        *(float4*)&ws[kwf][cwf + 4] = wb;
        __syncthreads();

        if (kt + KT < En) {
            xa = *(const float4*)(arow + kt + KT + khf);
            xb = *(const float4*)(arow + kt + KT + khf + 4);
            wa = *(const float4*)(wsrc + (size_t)(kt + KT + kwf) * LATn);
            wb = *(const float4*)(wsrc + (size_t)(kt + KT + kwf) * LATn + 4);
        }

#pragma unroll
        for (int kk = 0; kk < KT; kk++) {
            const ulonglong2* xp = (const ulonglong2*)&xs2[kk][m_base];
            ulonglong2 x01 = xp[0], x23 = xp[1], x45 = xp[2], x67 = xp[3];
            const ulonglong2* wp = (const ulonglong2*)&ws[kk][e_base];
            ulonglong2 w03 = wp[0], w47 = wp[1];
            u64t xd[8] = {x01.x, x01.y, x23.x, x23.y, x45.x, x45.y, x67.x, x67.y};
            u64t wpr[4] = {w03.x, w03.y, w47.x, w47.y};
#pragma unroll
            for (int i = 0; i < 8; i++)
#pragma unroll
                for (int j = 0; j < 4; j++)
                    acc[i][j] = ffma2(wpr[j], xd[i], acc[i][j]);
        }
        __syncthreads();
    }

    // epilogue: te<8 -> mu cols e_base..e_base+7 ; te>=8 -> var cols e_base-64..
    const bool  is_mu = (te < 8);
    const int   col0  = is_mu ? e_base : (e_base - 64);
    const float* bsrc = is_mu ? (b_mu + n * LATn + col0) : (b_var + n * LATn + col0);
    float* __restrict__ dst = is_mu ? mu_out : var_out;
    float4 ba = *(const float4*)(bsrc);
    float4 bb = *(const float4*)(bsrc + 4);
#pragma unroll
    for (int i = 0; i < 8; i++) {
        const size_t idx = ((size_t)(m_base + i) * Nn + n) * LATn + col0;
        float2 p0 = unpk(acc[i][0]), p1 = unpk(acc[i][1]);
        float2 p2 = unpk(acc[i][2]), p3 = unpk(acc[i][3]);
        float4 o0 = {p0.x + ba.x, p0.y + ba.y, p1.x + ba.z, p1.y + ba.w};
        float4 o1 = {p2.x + bb.x, p2.y + bb.y, p3.x + bb.z, p3.y + bb.w};
        *(float4*)(dst + idx)     = o0;
        *(float4*)(dst + idx + 4) = o1;
    }
}

// ---------------------------------------------------------------------------
// Launch
// ---------------------------------------------------------------------------
extern "C" void kernel_launch(void* const* d_in, const int* in_sizes, int n_in,
                              void* d_out, int out_size) {
    const float* x       = (const float*)d_in[0];
    const float* time_x  = (const float*)d_in[1];
    const float* W_embed = (const float*)d_in[2];
    const float* b_embed = (const float*)d_in[3];
    const float* W_mu    = (const float*)d_in[4];
    const float* b_mu    = (const float*)d_in[5];
    const float* W_var   = (const float*)d_in[6];
    const float* b_var   = (const float*)d_in[7];

    float* out  = (float*)d_out;
    float* h    = out;
    float* hhat = out + HN;
    float* mu   = out + 2 * HN;
    float* var  = out + 2 * HN + LATSZ;

    dim3 tgrid((Nn + 31) / 32, (Ln + 31) / 32, Bn);
    transpose_kernel<<<tgrid, dim3(32, 8)>>>(x);

    embed_kernel<<<Nn, 256>>>(W_embed, b_embed, time_x, h, hhat);

    heads_kernel<<<Nn, 256>>>(W_mu, b_mu, W_var, b_var, hhat, mu, var);
}